// round 1
// baseline (speedup 1.0000x reference)
#include <cuda_runtime.h>
#include <cstdint>
#include <math.h>

#define NB 128
#define NTOK 577
#define NP 576
#define DD 768
#define NG 17
#define NOCC 10
#define THREADS 576

typedef unsigned long long ull;

// ---- packed f32x2 helpers (sm_103a) ----
__device__ __forceinline__ ull pk2(float a, float b) {
    ull r; asm("mov.b64 %0, {%1,%2};" : "=l"(r) : "f"(a), "f"(b)); return r;
}
__device__ __forceinline__ void fma2(ull &acc, ull a, ull b) {
    asm("fma.rn.f32x2 %0, %1, %2, %0;" : "+l"(acc) : "l"(a), "l"(b));
}
__device__ __forceinline__ float hadd2(ull a) {
    return __uint_as_float((unsigned)a) + __uint_as_float((unsigned)(a >> 32));
}

// shared-memory layout (floats)
#define OFF_WT   0         // 17*768 = 13056 (transposed W: [g][d]); aliased by s_part in phase E
#define OFF_CLS  13056     // 768
#define OFF_SC   13824     // 17*576 = 9792 (scores -> masked attn)
#define OFF_SIM  23616     // 576
#define OFF_MASK 24192     // 576
#define OFF_RV   24768     // 576
#define OFF_RI   25344     // 576 (int)
#define OFF_MISC 25920     // 8
#define SMEM_FLOATS 25928

extern __shared__ float sm[];

__global__ void __launch_bounds__(THREADS, 1)
oag_kernel(const float* __restrict__ x, const float* __restrict__ gw,
           float* __restrict__ out) {
    const int b = blockIdx.x;
    const int tid = threadIdx.x;

    float* s_wt   = sm + OFF_WT;
    float* s_cls  = sm + OFF_CLS;
    float* s_sc   = sm + OFF_SC;
    float* s_sim  = sm + OFF_SIM;
    float* s_mask = sm + OFF_MASK;
    float* s_rv   = sm + OFF_RV;
    int*   s_ri   = (int*)(sm + OFF_RI);
    float* s_misc = sm + OFF_MISC;

    const size_t xb = (size_t)b * NTOK * DD;

    // ---- phase 0: stage W (transposed, d-contiguous per group) + cls ----
    for (int i = tid; i < DD * NG; i += THREADS) {
        int d = i / NG, g = i % NG;
        s_wt[g * DD + d] = gw[i];
    }
    for (int i = tid; i < DD; i += THREADS) s_cls[i] = x[xb + i];
    s_mask[tid] = 1.0f;
    __syncthreads();

    // cls inverse norm (block reduce)
    {
        float cp = 0.f;
        for (int i = tid; i < DD; i += THREADS) { float c = s_cls[i]; cp += c * c; }
        s_rv[tid] = cp; __syncthreads();
        if (tid < 64) s_rv[tid] += s_rv[tid + 512];
        __syncthreads();
        for (int s = 256; s >= 1; s >>= 1) {
            if (tid < s) s_rv[tid] += s_rv[tid + s];
            __syncthreads();
        }
        if (tid == 0) s_misc[0] = 1.0f / fmaxf(sqrtf(s_rv[0]), 1e-12f);
        __syncthreads();
    }
    const float rcls = s_misc[0];

    // ---- phase 1: fused sim + raw scores, one pass over x. patch p = tid ----
    {
        const int p = tid;
        const ulonglong2* xr =
            reinterpret_cast<const ulonglong2*>(x + xb + (size_t)(1 + p) * DD);
        ull acc[NG];
#pragma unroll
        for (int g = 0; g < NG; ++g) acc[g] = 0ull;
        ull dc = 0ull, nr = 0ull;
        ulonglong2 xv = xr[0];
#pragma unroll 2
        for (int it = 0; it < DD / 4; ++it) {
            ulonglong2 xn = xv;
            if (it + 1 < DD / 4) xn = xr[it + 1];
            const float* wd = s_wt + it * 4;
#pragma unroll
            for (int g = 0; g < NG; ++g) {
                ulonglong2 w = *reinterpret_cast<const ulonglong2*>(wd + g * DD);
                fma2(acc[g], xv.x, w.x);
                fma2(acc[g], xv.y, w.y);
            }
            ulonglong2 c = *reinterpret_cast<const ulonglong2*>(s_cls + it * 4);
            fma2(dc, xv.x, c.x); fma2(dc, xv.y, c.y);
            fma2(nr, xv.x, xv.x); fma2(nr, xv.y, xv.y);
            xv = xn;
        }
#pragma unroll
        for (int g = 0; g < NG; ++g) s_sc[g * NP + p] = hadd2(acc[g]);
        float dot = hadd2(dc), nrm = hadd2(nr);
        s_sim[p] = dot * (1.0f / fmaxf(sqrtf(nrm), 1e-12f)) * rcls;
    }
    __syncthreads();

    // ---- phase 2: 10x argmin over sims (tie -> lower index, matching top_k) ----
    for (int k = 0; k < NOCC; ++k) {
        s_rv[tid] = s_sim[tid]; s_ri[tid] = tid;
        __syncthreads();
        if (tid < 64) {
            float v2 = s_rv[tid + 512]; int i2 = s_ri[tid + 512];
            if (v2 < s_rv[tid] || (v2 == s_rv[tid] && i2 < s_ri[tid])) {
                s_rv[tid] = v2; s_ri[tid] = i2;
            }
        }
        __syncthreads();
        for (int s = 256; s >= 1; s >>= 1) {
            if (tid < s) {
                float v2 = s_rv[tid + s]; int i2 = s_ri[tid + s];
                if (v2 < s_rv[tid] || (v2 == s_rv[tid] && i2 < s_ri[tid])) {
                    s_rv[tid] = v2; s_ri[tid] = i2;
                }
            }
            __syncthreads();
        }
        if (tid == 0) {
            int m = s_ri[0];
            s_sim[m] = 3.4e38f;
            s_mask[m] = 0.f;
        }
        __syncthreads();
    }

    // ---- phase 3: softmax over g; masked patches -> attn 1/17, weight 0 ----
    {
        const int p = tid;
        const float mk = s_mask[p];
        float t[NG];
        float m = -3.4e38f;
#pragma unroll
        for (int g = 0; g < NG; ++g) {
            t[g] = s_sc[g * NP + p] * 10.0f;
            m = fmaxf(m, t[g]);
        }
        float ssum = 0.f;
#pragma unroll
        for (int g = 0; g < NG; ++g) { t[g] = __expf(t[g] - m); ssum += t[g]; }
        const float inv = 1.0f / ssum;
        float* oat = out + (size_t)NB * 18 * DD + (size_t)b * NG * NP;
#pragma unroll
        for (int g = 0; g < NG; ++g) {
            float a = t[g] * inv;
            oat[g * NP + p] = (mk != 0.f) ? a : (1.0f / 17.0f);
            s_sc[g * NP + p] = (mk != 0.f) ? a : 0.f;   // masked attn for phase E
        }
    }
    __syncthreads();

    // ---- phase E pass 1: group_features columns d = 0..575 (d = tid) ----
    {
        const int d = tid;
        const float* xp = x + xb + DD + d;   // patch 0, column d
        ull acc[NG];
#pragma unroll
        for (int g = 0; g < NG; ++g) acc[g] = 0ull;
        float c0 = xp[0 * DD], c1 = xp[1 * DD], c2 = xp[2 * DD], c3 = xp[3 * DD];
        for (int p4 = 0; p4 < NP; p4 += 4) {
            float n0 = c0, n1 = c1, n2 = c2, n3 = c3;
            if (p4 + 4 < NP) {
                n0 = xp[(p4 + 4) * DD]; n1 = xp[(p4 + 5) * DD];
                n2 = xp[(p4 + 6) * DD]; n3 = xp[(p4 + 7) * DD];
            }
            ull x01 = pk2(c0, c1), x23 = pk2(c2, c3);
            const float* ap = s_sc + p4;
#pragma unroll
            for (int g = 0; g < NG; ++g) {
                ulonglong2 a = *reinterpret_cast<const ulonglong2*>(ap + g * NP);
                fma2(acc[g], x01, a.x);
                fma2(acc[g], x23, a.y);
            }
            c0 = n0; c1 = n1; c2 = n2; c3 = n3;
        }
        float* of = out + (size_t)b * 18 * DD + DD + d;  // feats[b][1+g][d]
#pragma unroll
        for (int g = 0; g < NG; ++g) of[g * DD] = hadd2(acc[g]);
        out[(size_t)b * 18 * DD + d] = s_cls[d];         // feats[b][0][d]
    }

    // ---- phase E pass 2: columns 576..767, 3-way p-split, smem reduce ----
    {
        const int dd = tid % 192, part = tid / 192;      // part in 0..2
        const int d = 576 + dd;
        const float* xp = x + xb + DD + d;
        ull acc[NG];
#pragma unroll
        for (int g = 0; g < NG; ++g) acc[g] = 0ull;
        const int p0 = part * 192;
        for (int p4 = p0; p4 < p0 + 192; p4 += 4) {
            float c0 = xp[(p4 + 0) * DD], c1 = xp[(p4 + 1) * DD];
            float c2 = xp[(p4 + 2) * DD], c3 = xp[(p4 + 3) * DD];
            ull x01 = pk2(c0, c1), x23 = pk2(c2, c3);
            const float* ap = s_sc + p4;
#pragma unroll
            for (int g = 0; g < NG; ++g) {
                ulonglong2 a = *reinterpret_cast<const ulonglong2*>(ap + g * NP);
                fma2(acc[g], x01, a.x);
                fma2(acc[g], x23, a.y);
            }
        }
        float* s_part = s_wt;  // W no longer needed: alias as [part][g][192]
#pragma unroll
        for (int g = 0; g < NG; ++g)
            s_part[(part * NG + g) * 192 + dd] = hadd2(acc[g]);
    }
    __syncthreads();
    {
        const float* s_part = s_wt;
        for (int o = tid; o < NG * 192; o += THREADS) {
            float v = s_part[o] + s_part[NG * 192 + o] + s_part[2 * NG * 192 + o];
            int g = o / 192, dd = o % 192;
            out[(size_t)b * 18 * DD + (size_t)(1 + g) * DD + 576 + dd] = v;
        }
        if (tid < 192)
            out[(size_t)b * 18 * DD + 576 + tid] = s_cls[576 + tid];
    }
}

extern "C" void kernel_launch(void* const* d_in, const int* in_sizes, int n_in,
                              void* d_out, int out_size) {
    const float* x  = (const float*)d_in[0];
    const float* gw = (const float*)d_in[1];
    float* out = (float*)d_out;
    size_t smem = SMEM_FLOATS * sizeof(float);
    cudaFuncSetAttribute(oag_kernel, cudaFuncAttributeMaxDynamicSharedMemorySize,
                         (int)smem);
    oag_kernel<<<NB, THREADS, smem>>>(x, gw, out);
}

// round 2
// speedup vs baseline: 1.0131x; 1.0131x over previous
#include <cuda_runtime.h>
#include <cstdint>
#include <math.h>

#define NB 128
#define NTOK 577
#define NP 576
#define DD 768
#define NG 17
#define NGC 18          // 17 groups + cls row
#define NOCC 10
#define THREADS 768

typedef unsigned long long ull;

// ---- packed f32x2 helpers (sm_103a) ----
__device__ __forceinline__ ull pk2(float a, float b) {
    ull r; asm("mov.b64 %0, {%1,%2};" : "=l"(r) : "f"(a), "f"(b)); return r;
}
__device__ __forceinline__ void fma2(ull &acc, ull a, ull b) {
    asm("fma.rn.f32x2 %0, %1, %2, %0;" : "+l"(acc) : "l"(a), "l"(b));
}
__device__ __forceinline__ float hadd2(ull a) {
    return __uint_as_float((unsigned)a) + __uint_as_float((unsigned)(a >> 32));
}

// shared-memory layout (floats)
#define OFF_WT   0                 // 18*768 = 13824 ([g][d], g=17 is cls)
#define OFF_SC   13824             // 17*576 = 9792 (scores -> masked attn)
#define OFF_SIM  23616             // 576
#define OFF_MASK 24192             // 576
#define SMEM_FLOATS 24768

extern __shared__ float sm[];

__global__ void __launch_bounds__(THREADS, 1)
oag_kernel(const float* __restrict__ x, const float* __restrict__ gw,
           float* __restrict__ out) {
    const int b   = blockIdx.x;
    const int tid = threadIdx.x;

    float* s_wt   = sm + OFF_WT;
    float* s_sc   = sm + OFF_SC;
    float* s_sim  = sm + OFF_SIM;
    float* s_mask = sm + OFF_MASK;

    const size_t xb = (size_t)b * NTOK * DD;

    // ---- phase 0: stage W^T ([g][d]) + cls as group 17 ----
    for (int i = tid; i < DD * NG; i += THREADS) {
        int d = i / NG, g = i % NG;
        s_wt[g * DD + d] = gw[i];
    }
    for (int i = tid; i < DD; i += THREADS) s_wt[NG * DD + i] = x[xb + i];
    if (tid < NP) s_mask[tid] = 1.0f;
    __syncthreads();

    // ---- phase 1: fused (sim numerator, patch norm, raw scores), one pass over x ----
    if (tid < NP) {
        const int p = tid;
        const float4* xr = reinterpret_cast<const float4*>(x + xb + (size_t)(1 + p) * DD);
        ull acc[NGC];
#pragma unroll
        for (int g = 0; g < NGC; ++g) acc[g] = 0ull;
        ull nr = 0ull;

        // distance-2 pipeline: 2 double-float4 buffers, unroll 2
        float4 bA0 = xr[0], bA1 = xr[1], bB0 = xr[2], bB1 = xr[3];
#pragma unroll 2
        for (int it = 0; it < DD / 8; ++it) {            // 96 iterations, 8 floats each
            float4 v0, v1;
            if ((it & 1) == 0) { v0 = bA0; v1 = bA1;
                if (it + 2 < DD / 8) { bA0 = xr[2 * it + 4]; bA1 = xr[2 * it + 5]; } }
            else               { v0 = bB0; v1 = bB1;
                if (it + 2 < DD / 8) { bB0 = xr[2 * it + 4]; bB1 = xr[2 * it + 5]; } }
            ull xa01 = pk2(v0.x, v0.y), xa23 = pk2(v0.z, v0.w);
            ull xb01 = pk2(v1.x, v1.y), xb23 = pk2(v1.z, v1.w);
            const float* wd = s_wt + it * 8;
#pragma unroll
            for (int g = 0; g < NGC; ++g) {
                const ulonglong2* wp = reinterpret_cast<const ulonglong2*>(wd + g * DD);
                ulonglong2 w0 = wp[0], w1 = wp[1];
                fma2(acc[g], xa01, w0.x); fma2(acc[g], xa23, w0.y);
                fma2(acc[g], xb01, w1.x); fma2(acc[g], xb23, w1.y);
            }
            fma2(nr, xa01, xa01); fma2(nr, xa23, xa23);
            fma2(nr, xb01, xb01); fma2(nr, xb23, xb23);
        }
#pragma unroll
        for (int g = 0; g < NG; ++g) s_sc[g * NP + p] = hadd2(acc[g]);
        float dot = hadd2(acc[NG]);
        float nrm = hadd2(nr);
        // cls-norm factor is a positive per-batch constant: ordering-invariant, dropped
        s_sim[p] = dot / fmaxf(sqrtf(nrm), 1e-12f);
    }
    __syncthreads();

    // ---- phase 2: 10x argmin within warp 0 (576 = 32 lanes x 18) ----
    if (tid < 32) {
        for (int k = 0; k < NOCC; ++k) {
            float best = 3.4e38f; int bi = NP;
#pragma unroll
            for (int j = 0; j < NP / 32; ++j) {
                int idx = tid + j * 32;
                float v = s_sim[idx];
                if (v < best || (v == best && idx < bi)) { best = v; bi = idx; }
            }
#pragma unroll
            for (int off = 16; off; off >>= 1) {
                float ov = __shfl_down_sync(0xffffffffu, best, off);
                int   oi = __shfl_down_sync(0xffffffffu, bi, off);
                if (ov < best || (ov == best && oi < bi)) { best = ov; bi = oi; }
            }
            bi = __shfl_sync(0xffffffffu, bi, 0);
            if (tid == 0) { s_sim[bi] = 3.4e38f; s_mask[bi] = 0.0f; }
            __syncwarp();
        }
    }
    __syncthreads();

    // ---- phase 3: softmax over g; masked -> attn 1/17 (out), weight 0 (smem) ----
    if (tid < NP) {
        const int p = tid;
        const float mk = s_mask[p];
        float t[NG];
        float m = -3.4e38f;
#pragma unroll
        for (int g = 0; g < NG; ++g) {
            t[g] = s_sc[g * NP + p] * 10.0f;
            m = fmaxf(m, t[g]);
        }
        float ssum = 0.f;
#pragma unroll
        for (int g = 0; g < NG; ++g) { t[g] = __expf(t[g] - m); ssum += t[g]; }
        const float inv = 1.0f / ssum;
        float* oat = out + (size_t)NB * NGC * DD + (size_t)b * NG * NP;
#pragma unroll
        for (int g = 0; g < NG; ++g) {
            float a = t[g] * inv;
            oat[g * NP + p] = (mk != 0.f) ? a : (1.0f / 17.0f);
            s_sc[g * NP + p] = (mk != 0.f) ? a : 0.f;
        }
    }
    __syncthreads();

    // ---- phase E: group_features, single pass, d = tid (all 768 threads) ----
    {
        const int d = tid;
        const float* xp = x + xb + DD + d;
        ull acc[NG];
#pragma unroll
        for (int g = 0; g < NG; ++g) acc[g] = 0ull;

        float a0 = xp[0 * (size_t)DD], a1 = xp[1 * (size_t)DD];
        float a2 = xp[2 * (size_t)DD], a3 = xp[3 * (size_t)DD];
        float b0 = xp[4 * (size_t)DD], b1 = xp[5 * (size_t)DD];
        float b2 = xp[6 * (size_t)DD], b3 = xp[7 * (size_t)DD];

        for (int p4 = 0; p4 < NP; p4 += 8) {
            // stage A: patches p4..p4+3; prefetch p4+8..p4+11
            float n0 = 0.f, n1 = 0.f, n2 = 0.f, n3 = 0.f;
            if (p4 + 8 < NP) {
                n0 = xp[(size_t)(p4 +  8) * DD]; n1 = xp[(size_t)(p4 +  9) * DD];
                n2 = xp[(size_t)(p4 + 10) * DD]; n3 = xp[(size_t)(p4 + 11) * DD];
            }
            {
                ull x01 = pk2(a0, a1), x23 = pk2(a2, a3);
                const float* ap = s_sc + p4;
#pragma unroll
                for (int g = 0; g < NG; ++g) {
                    ulonglong2 at = *reinterpret_cast<const ulonglong2*>(ap + g * NP);
                    fma2(acc[g], x01, at.x);
                    fma2(acc[g], x23, at.y);
                }
            }
            a0 = n0; a1 = n1; a2 = n2; a3 = n3;

            // stage B: patches p4+4..p4+7; prefetch p4+12..p4+15
            n0 = n1 = n2 = n3 = 0.f;
            if (p4 + 12 < NP) {
                n0 = xp[(size_t)(p4 + 12) * DD]; n1 = xp[(size_t)(p4 + 13) * DD];
                n2 = xp[(size_t)(p4 + 14) * DD]; n3 = xp[(size_t)(p4 + 15) * DD];
            }
            {
                ull x01 = pk2(b0, b1), x23 = pk2(b2, b3);
                const float* ap = s_sc + p4 + 4;
#pragma unroll
                for (int g = 0; g < NG; ++g) {
                    ulonglong2 at = *reinterpret_cast<const ulonglong2*>(ap + g * NP);
                    fma2(acc[g], x01, at.x);
                    fma2(acc[g], x23, at.y);
                }
            }
            b0 = n0; b1 = n1; b2 = n2; b3 = n3;
        }

        float* of = out + (size_t)b * NGC * DD + d;
        of[0] = x[xb + d];                       // feats[b][0][d] = cls
#pragma unroll
        for (int g = 0; g < NG; ++g) of[(size_t)(1 + g) * DD] = hadd2(acc[g]);
    }
}

extern "C" void kernel_launch(void* const* d_in, const int* in_sizes, int n_in,
                              void* d_out, int out_size) {
    const float* x  = (const float*)d_in[0];
    const float* gw = (const float*)d_in[1];
    float* out = (float*)d_out;
    size_t smem = SMEM_FLOATS * sizeof(float);
    cudaFuncSetAttribute(oag_kernel, cudaFuncAttributeMaxDynamicSharedMemorySize,
                         (int)smem);
    oag_kernel<<<NB, THREADS, smem>>>(x, gw, out);
}